// round 12
// baseline (speedup 1.0000x reference)
#include <cuda_runtime.h>
#include <cuda_bf16.h>
#include <cstdint>

// Problem dims (fixed by dataset)
#define PN0 10000
#define PN1 100000
#define PN2 1000000
#define PE0 100000
#define PE1 1000000
#define PDIN 128
#define PDH  256
#define PDOUT 47

#define NCHUNK 4

// ---------------- scratch (device globals; no allocation allowed) -------------
__device__ float g_sum1[PN1 * PDIN];     // a1 in-place after finalize
__device__ float g_deg1[PN1];
__device__ float g_n1[PN1 * PDH];
__device__ float g_sum0[PN0 * PDIN];     // a0 in-place
__device__ float g_deg0[PN0];
__device__ float g_n0[PN0 * PDH];
__device__ float g_sumA[PN0 * PDH];      // final a in-place

__device__ unsigned g_mask_h2 [PN2 * PDIN / 32];
__device__ unsigned g_mask_h1s[PN1 * PDIN / 32];
__device__ unsigned g_mask_h1f[PN1 * PDIN / 32];
__device__ unsigned g_mask_h0 [PN0 * PDIN / 32];
__device__ unsigned g_mask_n1 [PN1 * PDH  / 32];
__device__ unsigned g_mask_n0 [PN0 * PDH  / 32];
__device__ unsigned g_flag2  [PN2];      // h2 row-claim flags
__device__ unsigned g_flag1  [PN1];      // h1s/mn1 row-claim flags (src0 rows)

// ---------------- threefry2x32 (JAX-exact, 20 rounds) ------------------------
__host__ __device__ __forceinline__ void tf2x32(unsigned k0, unsigned k1,
                                                unsigned x0, unsigned x1,
                                                unsigned &o0, unsigned &o1) {
  unsigned ks2 = k0 ^ k1 ^ 0x1BD11BDAu;
#ifdef __CUDA_ARCH__
#define TF_ROT(x, r) __funnelshift_l((x), (x), (r))
#else
#define TF_ROT(x, r) (((x) << (r)) | ((x) >> (32 - (r))))
#endif
#define TF_RND(r) { x0 += x1; x1 = TF_ROT(x1, r); x1 ^= x0; }
  x0 += k0; x1 += k1;
  TF_RND(13) TF_RND(15) TF_RND(26) TF_RND(6)
  x0 += k1;  x1 += ks2 + 1u;
  TF_RND(17) TF_RND(29) TF_RND(16) TF_RND(24)
  x0 += ks2; x1 += k0 + 2u;
  TF_RND(13) TF_RND(15) TF_RND(26) TF_RND(6)
  x0 += k0;  x1 += k1 + 3u;
  TF_RND(17) TF_RND(29) TF_RND(16) TF_RND(24)
  x0 += k1;  x1 += ks2 + 4u;
  TF_RND(13) TF_RND(15) TF_RND(26) TF_RND(6)
  x0 += ks2; x1 += k0 + 5u;
#undef TF_RND
#undef TF_ROT
  o0 = x0; o1 = x1;
}

// ---------------- dense maskgen (ILP=4) ---------------------------------------
__global__ __launch_bounds__(256) void maskgen4_kernel(unsigned k0, unsigned k1,
                                                       unsigned total,
                                                       unsigned *__restrict__ mask) {
  unsigned j0 = blockIdx.x * 1024u + threadIdx.x;
  unsigned keep[4];
#pragma unroll
  for (int k = 0; k < 4; k++) {
    unsigned o0, o1;
    tf2x32(k0, k1, 0u, j0 + k * 256u, o0, o1);
    keep[k] = !((o0 ^ o1) >> 31);
  }
#pragma unroll
  for (int k = 0; k < 4; k++) {
    unsigned j = j0 + k * 256u;
    unsigned b = __ballot_sync(0xffffffffu, keep[k]);
    if ((threadIdx.x & 31) == 0 && j < total) mask[j >> 5] = b;
  }
}

// ---------------- h2 maskgen: only rows referenced by src (claim-based) ------
// Chunk-safe: a row's mask is written by the claim at its FIRST occurrence in
// edge order, which is always in a chunk <= the chunk of any reader.
__global__ __launch_bounds__(256) void maskgen_h2_kernel(
    unsigned k0, unsigned k1, const int *__restrict__ src, int E,
    unsigned *__restrict__ flag, unsigned *__restrict__ mask) {
  int e = (blockIdx.x * blockDim.x + threadIdx.x) >> 5;
  if (e >= E) return;
  int lane = threadIdx.x & 31;
  int r = src[e];
  unsigned claimed = 0;
  if (lane == 0) claimed = (atomicExch(&flag[r], 1u) == 0u);
  claimed = __shfl_sync(0xffffffffu, claimed, 0);
  if (!claimed) return;
  unsigned base = (unsigned)r * 128u + (unsigned)lane;
  unsigned keep[4];
#pragma unroll
  for (int k = 0; k < 4; k++) {
    unsigned o0, o1;
    tf2x32(k0, k1, 0u, base + 32u * k, o0, o1);
    keep[k] = !((o0 ^ o1) >> 31);
  }
#pragma unroll
  for (int k = 0; k < 4; k++) {
    unsigned b = __ballot_sync(0xffffffffu, keep[k]);
    if (lane == 0) mask[r * 4 + k] = b;
  }
}

// ---------------- combined claim maskgen for h1s (4 words) + mn1 (8 words) ----
__global__ __launch_bounds__(256) void maskgen_pair_kernel(
    unsigned a0, unsigned a1, unsigned b0, unsigned b1,
    const int *__restrict__ src, int E, unsigned *__restrict__ flag,
    unsigned *__restrict__ maskA, unsigned *__restrict__ maskB) {
  int e = (blockIdx.x * blockDim.x + threadIdx.x) >> 5;
  if (e >= E) return;
  int lane = threadIdx.x & 31;
  int r = src[e];
  unsigned claimed = 0;
  if (lane == 0) claimed = (atomicExch(&flag[r], 1u) == 0u);
  claimed = __shfl_sync(0xffffffffu, claimed, 0);
  if (!claimed) return;
  unsigned baseA = (unsigned)r * 128u + (unsigned)lane;
  unsigned baseB = (unsigned)r * 256u + (unsigned)lane;
  unsigned keepA[4], keepB[8];
#pragma unroll
  for (int k = 0; k < 4; k++) {
    unsigned o0, o1;
    tf2x32(a0, a1, 0u, baseA + 32u * k, o0, o1);
    keepA[k] = !((o0 ^ o1) >> 31);
  }
#pragma unroll
  for (int k = 0; k < 8; k++) {
    unsigned o0, o1;
    tf2x32(b0, b1, 0u, baseB + 32u * k, o0, o1);
    keepB[k] = !((o0 ^ o1) >> 31);
  }
#pragma unroll
  for (int k = 0; k < 4; k++) {
    unsigned b = __ballot_sync(0xffffffffu, keepA[k]);
    if (lane == 0) maskA[r * 4 + k] = b;
  }
#pragma unroll
  for (int k = 0; k < 8; k++) {
    unsigned b = __ballot_sync(0xffffffffu, keepB[k]);
    if (lane == 0) maskB[r * 8 + k] = b;
  }
}

// ---------------- edge gather + segment-sum (one warp per edge) --------------
__global__ __launch_bounds__(256) void edge_gather_kernel(
    const float *__restrict__ feat, const int *__restrict__ rowmap,
    const int *__restrict__ src, const int *__restrict__ dst,
    const unsigned *__restrict__ mask, float *__restrict__ sum,
    float *__restrict__ deg, int E, int C) {
  int e = (blockIdx.x * blockDim.x + threadIdx.x) >> 5;
  if (e >= E) return;
  int lane = threadIdx.x & 31;
  int r = src[e];
  int d = dst[e];
  size_t g = rowmap ? (size_t)rowmap[r] : (size_t)r;
  if (deg && lane == 0) atomicAdd(&deg[d], 1.0f);
  const float4 *fr = reinterpret_cast<const float4 *>(feat + g * (size_t)C);
  for (int c0 = lane * 4; c0 < C; c0 += 128) {
    float4 v = fr[c0 >> 2];
    unsigned mw = mask[r * (C >> 5) + (c0 >> 5)];
    int sh = c0 & 31;
    float a0 = ((mw >> (sh + 0)) & 1u) ? 2.0f * v.x : 0.0f;
    float a1 = ((mw >> (sh + 1)) & 1u) ? 2.0f * v.y : 0.0f;
    float a2 = ((mw >> (sh + 2)) & 1u) ? 2.0f * v.z : 0.0f;
    float a3 = ((mw >> (sh + 3)) & 1u) ? 2.0f * v.w : 0.0f;
    float *s = sum + (size_t)d * C + c0;
    asm volatile("red.global.add.v4.f32 [%0], {%1,%2,%3,%4};"
                 :: "l"(s), "f"(a0), "f"(a1), "f"(a2), "f"(a3) : "memory");
  }
}

// ---------------- finalize: relu(sum/deg + dropout(self)) in-place -----------
__global__ __launch_bounds__(256) void finalize_kernel(
    float *__restrict__ sum, const float *__restrict__ deg,
    const float *__restrict__ selfFeat, const int *__restrict__ rowmap,
    const unsigned *__restrict__ maskSelf, int Nr, int C) {
  int idx = blockIdx.x * blockDim.x + threadIdx.x;
  int perRow = C >> 2;
  if (idx >= Nr * perRow) return;
  int i = idx / perRow;
  int c0 = (idx - i * perRow) << 2;
  float d = deg[i];
  float inv = d > 0.f ? 1.0f / d : 0.f;
  size_t g = rowmap ? (size_t)rowmap[i] : (size_t)i;
  float4 hv = *reinterpret_cast<const float4 *>(selfFeat + g * (size_t)C + c0);
  unsigned mw = maskSelf[i * (C >> 5) + (c0 >> 5)];
  int sh = c0 & 31;
  float4 sv = *reinterpret_cast<const float4 *>(sum + (size_t)i * C + c0);
  float r0 = sv.x * inv + (((mw >> (sh + 0)) & 1u) ? 2.f * hv.x : 0.f);
  float r1 = sv.y * inv + (((mw >> (sh + 1)) & 1u) ? 2.f * hv.y : 0.f);
  float r2 = sv.z * inv + (((mw >> (sh + 2)) & 1u) ? 2.f * hv.z : 0.f);
  float r3 = sv.w * inv + (((mw >> (sh + 3)) & 1u) ? 2.f * hv.w : 0.f);
  float4 o = make_float4(fmaxf(r0, 0.f), fmaxf(r1, 0.f),
                         fmaxf(r2, 0.f), fmaxf(r3, 0.f));
  *reinterpret_cast<float4 *>(sum + (size_t)i * C + c0) = o;
}

// ---------------- SGEMM 128x128 tile, 8x8 microtile, BK=8, bias --------------
// A: [M,K] row-major, B: [K,N] row-major. K multiple of 8.
// B rows are loaded with float4 ONLY when N % 4 == 0 (16B-aligned rows);
// otherwise scalar loads (the N=47 GEMM is tiny, alignment trap otherwise).
__global__ __launch_bounds__(256) void sgemm_bias_128x128(
    const float *__restrict__ A, const float *__restrict__ B,
    const float *__restrict__ bias, float *__restrict__ C,
    int M, int N, int K) {
  __shared__ float As[8][132];   // [k][m]
  __shared__ float Bs[8][132];   // [k][n]
  int tid = threadIdx.x;
  int row0 = blockIdx.y * 128;
  int col0 = blockIdx.x * 128;
  int tr = tid >> 4;        // 0..15 -> rows tr*8..+7
  int tc = tid & 15;        // 0..15 -> cols tc*8..+7
  float acc[8][8];
#pragma unroll
  for (int i = 0; i < 8; i++)
#pragma unroll
    for (int j = 0; j < 8; j++) acc[i][j] = 0.f;

  int ar = tid >> 1;          // 0..127
  int ak = (tid & 1) * 4;     // 0 or 4
  int bk = tid >> 5;          // 0..7
  int bc = (tid & 31) * 4;    // 0..124
  bool nvec = ((N & 3) == 0);

  for (int kk = 0; kk < K; kk += 8) {
    float4 av;
    if (row0 + ar < M)
      av = *reinterpret_cast<const float4 *>(A + (size_t)(row0 + ar) * K + kk + ak);
    else
      av = make_float4(0.f, 0.f, 0.f, 0.f);
    As[ak + 0][ar] = av.x; As[ak + 1][ar] = av.y;
    As[ak + 2][ar] = av.z; As[ak + 3][ar] = av.w;
    {
      float4 bv;
      int c = col0 + bc;
      const float *brow = B + (size_t)(kk + bk) * N;
      if (nvec && c + 3 < N)
        bv = *reinterpret_cast<const float4 *>(brow + c);
      else {
        bv.x = (c + 0 < N) ? brow[c + 0] : 0.f;
        bv.y = (c + 1 < N) ? brow[c + 1] : 0.f;
        bv.z = (c + 2 < N) ? brow[c + 2] : 0.f;
        bv.w = (c + 3 < N) ? brow[c + 3] : 0.f;
      }
      *reinterpret_cast<float4 *>(&Bs[bk][bc]) = bv;
    }
    __syncthreads();
#pragma unroll
    for (int k = 0; k < 8; k++) {
      float a8[8], b8[8];
      *reinterpret_cast<float4 *>(a8)     = *reinterpret_cast<const float4 *>(&As[k][tr * 8]);
      *reinterpret_cast<float4 *>(a8 + 4) = *reinterpret_cast<const float4 *>(&As[k][tr * 8 + 4]);
      *reinterpret_cast<float4 *>(b8)     = *reinterpret_cast<const float4 *>(&Bs[k][tc * 8]);
      *reinterpret_cast<float4 *>(b8 + 4) = *reinterpret_cast<const float4 *>(&Bs[k][tc * 8 + 4]);
#pragma unroll
      for (int i = 0; i < 8; i++)
#pragma unroll
        for (int j = 0; j < 8; j++) acc[i][j] += a8[i] * b8[j];
    }
    __syncthreads();
  }
#pragma unroll
  for (int i = 0; i < 8; i++) {
    int r = row0 + tr * 8 + i;
    if (r >= M) continue;
#pragma unroll
    for (int j = 0; j < 8; j++) {
      int c = col0 + tc * 8 + j;
      if (c < N) C[(size_t)r * N + c] = acc[i][j] + bias[c];
    }
  }
}

// ---------------- host orchestration (chunk-pipelined, multi-stream) ----------
extern "C" void kernel_launch(void *const *d_in, const int *in_sizes, int n_in,
                              void *d_out, int out_size) {
  const float *features = (const float *)d_in[0];
  const int *s0 = (const int *)d_in[1];
  const int *s1 = (const int *)d_in[2];
  const int *s2 = (const int *)d_in[3];
  const int *src0 = (const int *)d_in[4];
  const int *dst0 = (const int *)d_in[5];
  const int *src1 = (const int *)d_in[6];
  const int *dst1 = (const int *)d_in[7];
  const float *W1 = (const float *)d_in[8];
  const float *b1 = (const float *)d_in[9];
  const float *W2 = (const float *)d_in[10];
  const float *b2 = (const float *)d_in[11];
  float *out = (float *)d_out;

  const int n0 = in_sizes[1];
  const int n1 = in_sizes[2];
  const int n2 = in_sizes[3];
  const int e0 = in_sizes[4];
  const int e1 = in_sizes[6];
  const int dh = in_sizes[9];          // 256
  const int dout = in_sizes[11];       // 47
  const int din = in_sizes[8] / dh;    // 128

  // ---- JAX key chain, threefry_partitionable=True semantics ----
  unsigned dk[3][2];
  tf2x32(0u, 42u, 0u, 0u, dk[0][0], dk[0][1]);
  tf2x32(0u, 42u, 0u, 1u, dk[1][0], dk[1][1]);
  tf2x32(0u, 42u, 0u, 2u, dk[2][0], dk[2][1]);
  unsigned kSrc[3][2], kSelf[3][2];
  for (int i = 0; i < 3; i++) {
    tf2x32(dk[i][0], dk[i][1], 0u, 0u, kSrc[i][0], kSrc[i][1]);
    tf2x32(dk[i][0], dk[i][1], 0u, 1u, kSelf[i][0], kSelf[i][1]);
  }

  // ---- scratch addresses ----
  void *p_sum1, *p_deg1, *p_n1, *p_sum0, *p_deg0, *p_n0, *p_sumA;
  void *p_flag2, *p_flag1;
  void *p_mh2, *p_mh1s, *p_mh1f, *p_mh0, *p_mn1, *p_mn0;
  cudaGetSymbolAddress(&p_sum1, g_sum1);
  cudaGetSymbolAddress(&p_deg1, g_deg1);
  cudaGetSymbolAddress(&p_n1, g_n1);
  cudaGetSymbolAddress(&p_sum0, g_sum0);
  cudaGetSymbolAddress(&p_deg0, g_deg0);
  cudaGetSymbolAddress(&p_n0, g_n0);
  cudaGetSymbolAddress(&p_sumA, g_sumA);
  cudaGetSymbolAddress(&p_flag2, g_flag2);
  cudaGetSymbolAddress(&p_flag1, g_flag1);
  cudaGetSymbolAddress(&p_mh2, g_mask_h2);
  cudaGetSymbolAddress(&p_mh1s, g_mask_h1s);
  cudaGetSymbolAddress(&p_mh1f, g_mask_h1f);
  cudaGetSymbolAddress(&p_mh0, g_mask_h0);
  cudaGetSymbolAddress(&p_mn1, g_mask_n1);
  cudaGetSymbolAddress(&p_mn0, g_mask_n0);

  // ---- streams / events (created once; capture-safe fork/join pattern) ----
  static cudaStream_t sB = nullptr, sC = nullptr;
  static cudaEvent_t evFork = nullptr, evZ = nullptr, evSrcMasks = nullptr,
                     evH1f = nullptr, evB = nullptr, evC = nullptr;
  static cudaEvent_t evM[NCHUNK] = {};
  if (!sB) {
    cudaStreamCreateWithFlags(&sB, cudaStreamNonBlocking);
    cudaStreamCreateWithFlags(&sC, cudaStreamNonBlocking);
    cudaEventCreateWithFlags(&evFork, cudaEventDisableTiming);
    cudaEventCreateWithFlags(&evZ, cudaEventDisableTiming);
    cudaEventCreateWithFlags(&evSrcMasks, cudaEventDisableTiming);
    cudaEventCreateWithFlags(&evH1f, cudaEventDisableTiming);
    cudaEventCreateWithFlags(&evB, cudaEventDisableTiming);
    cudaEventCreateWithFlags(&evC, cudaEventDisableTiming);
    for (int i = 0; i < NCHUNK; i++)
      cudaEventCreateWithFlags(&evM[i], cudaEventDisableTiming);
  }
  cudaStream_t S = 0;  // legacy default = capture/origin stream

  // ---- S: flag memsets, then fork ----
  cudaMemsetAsync(p_flag2, 0, (size_t)n2 * sizeof(unsigned), S);
  cudaMemsetAsync(p_flag1, 0, (size_t)n1 * sizeof(unsigned), S);
  cudaEventRecord(evFork, S);

  // ---- sB: h2 maskgen in NCHUNK chunks (ALU), then src-masks, h0, n0 ----
  cudaStreamWaitEvent(sB, evFork, 0);
  {
    int chunk = (e1 + NCHUNK - 1) / NCHUNK;
    for (int i = 0; i < NCHUNK; i++) {
      int base = i * chunk;
      int cnt = (base + chunk <= e1) ? chunk : (e1 - base);
      if (cnt > 0) {
        int blocks = (cnt * 32 + 255) / 256;
        maskgen_h2_kernel<<<blocks, 256, 0, sB>>>(
            kSrc[1][0], kSrc[1][1], src1 + base, cnt,
            (unsigned *)p_flag2, (unsigned *)p_mh2);
      }
      cudaEventRecord(evM[i], sB);
    }
  }
  {
    int blocks = (e0 * 32 + 255) / 256;
    maskgen_pair_kernel<<<blocks, 256, 0, sB>>>(
        kSrc[0][0], kSrc[0][1], kSrc[2][0], kSrc[2][1], src0, e0,
        (unsigned *)p_flag1, (unsigned *)p_mh1s, (unsigned *)p_mn1);
  }
  cudaEventRecord(evSrcMasks, sB);
  {
    unsigned total = (unsigned)n0 * din;   // h0 self
    maskgen4_kernel<<<(total + 1023u) / 1024u, 256, 0, sB>>>(
        kSelf[0][0], kSelf[0][1], total, (unsigned *)p_mh0);
  }
  {
    unsigned total = (unsigned)n0 * dh;    // n0 self
    maskgen4_kernel<<<(total + 1023u) / 1024u, 256, 0, sB>>>(
        kSelf[2][0], kSelf[2][1], total, (unsigned *)p_mn0);
  }
  cudaEventRecord(evB, sB);

  // ---- sC: accumulator memsets (memory) + h1f self mask ----
  cudaStreamWaitEvent(sC, evFork, 0);
  cudaMemsetAsync(p_sum1, 0, (size_t)n1 * din * sizeof(float), sC);
  cudaMemsetAsync(p_deg1, 0, (size_t)n1 * sizeof(float), sC);
  cudaMemsetAsync(p_sum0, 0, (size_t)n0 * din * sizeof(float), sC);
  cudaMemsetAsync(p_deg0, 0, (size_t)n0 * sizeof(float), sC);
  cudaMemsetAsync(p_sumA, 0, (size_t)n0 * dh * sizeof(float), sC);
  cudaEventRecord(evZ, sC);
  {
    unsigned total = (unsigned)n1 * din;   // h1f (self mask for finalize1)
    maskgen4_kernel<<<(total + 1023u) / 1024u, 256, 0, sC>>>(
        kSelf[1][0], kSelf[1][1], total, (unsigned *)p_mh1f);
  }
  cudaEventRecord(evH1f, sC);

  // ---- S: gather1 in chunks, pipelined against sB's maskgen chunks ----
  cudaStreamWaitEvent(S, evZ, 0);
  {
    int chunk = (e1 + NCHUNK - 1) / NCHUNK;
    for (int i = 0; i < NCHUNK; i++) {
      int base = i * chunk;
      int cnt = (base + chunk <= e1) ? chunk : (e1 - base);
      cudaStreamWaitEvent(S, evM[i], 0);
      if (cnt > 0) {
        int blocks = (cnt * 32 + 255) / 256;
        edge_gather_kernel<<<blocks, 256, 0, S>>>(
            features, s2, src1 + base, dst1 + base, (unsigned *)p_mh2,
            (float *)p_sum1, (float *)p_deg1, cnt, din);
      }
    }
  }
  cudaStreamWaitEvent(S, evH1f, 0);
  {
    int fb = (n1 * (din / 4) + 255) / 256;
    finalize_kernel<<<fb, 256, 0, S>>>((float *)p_sum1, (float *)p_deg1,
                                       features, s1, (unsigned *)p_mh1f, n1,
                                       din);
    dim3 grid((dh + 127) / 128, (n1 + 127) / 128);
    sgemm_bias_128x128<<<grid, 256, 0, S>>>((float *)p_sum1, W1, b1,
                                            (float *)p_n1, n1, dh, din);
  }

  // ---- sC: a0 branch (concurrent with gather1/gemm1 on S) ----
  cudaStreamWaitEvent(sC, evSrcMasks, 0);
  {
    int blocks = (e0 * 32 + 255) / 256;
    edge_gather_kernel<<<blocks, 256, 0, sC>>>(features, s1, src0, dst0,
                                               (unsigned *)p_mh1s,
                                               (float *)p_sum0,
                                               (float *)p_deg0, e0, din);
  }
  cudaStreamWaitEvent(sC, evB, 0);  // h0 mask ready
  {
    int fb = (n0 * (din / 4) + 255) / 256;
    finalize_kernel<<<fb, 256, 0, sC>>>((float *)p_sum0, (float *)p_deg0,
                                        features, s0, (unsigned *)p_mh0, n0,
                                        din);
    dim3 grid((dh + 127) / 128, (n0 + 127) / 128);
    sgemm_bias_128x128<<<grid, 256, 0, sC>>>((float *)p_sum0, W1, b1,
                                             (float *)p_n0, n0, dh, din);
  }
  cudaEventRecord(evC, sC);

  // ---- S: final layer ----
  cudaStreamWaitEvent(S, evSrcMasks, 0);  // mn1 mask
  {
    int blocks = (e0 * 32 + 255) / 256;
    edge_gather_kernel<<<blocks, 256, 0, S>>>((float *)p_n1, nullptr, src0,
                                              dst0, (unsigned *)p_mn1,
                                              (float *)p_sumA, nullptr, e0, dh);
  }
  cudaStreamWaitEvent(S, evC, 0);  // n0 + deg0 ready
  cudaStreamWaitEvent(S, evB, 0);  // mn0 mask ready
  {
    int fb = (n0 * (dh / 4) + 255) / 256;
    finalize_kernel<<<fb, 256, 0, S>>>((float *)p_sumA, (float *)p_deg0,
                                       (float *)p_n0, nullptr,
                                       (unsigned *)p_mn0, n0, dh);
    dim3 grid((dout + 127) / 128, (n0 + 127) / 128);
    sgemm_bias_128x128<<<grid, 256, 0, S>>>((float *)p_sumA, W2, b2, out, n0,
                                            dout, dh);
  }
}

// round 14
// speedup vs baseline: 1.1370x; 1.1370x over previous
#include <cuda_runtime.h>
#include <cuda_bf16.h>
#include <cstdint>

// Problem dims (fixed by dataset)
#define PN0 10000
#define PN1 100000
#define PN2 1000000
#define PE0 100000
#define PE1 1000000
#define PDIN 128
#define PDH  256
#define PDOUT 47

// ---------------- scratch (device globals; no allocation allowed) -------------
__device__ float g_sum1[PN1 * PDIN];     // a1 in-place after finalize
__device__ float g_deg1[PN1];
__device__ float g_n1[PN1 * PDH];
__device__ float g_sum0[PN0 * PDIN];     // a0 in-place
__device__ float g_deg0[PN0];
__device__ float g_n0[PN0 * PDH];
__device__ float g_sumA[PN0 * PDH];      // final a in-place

__device__ unsigned g_mask_h2 [PN2 * PDIN / 32];
__device__ unsigned g_mask_h1s[PN1 * PDIN / 32];
__device__ unsigned g_mask_n1 [PN1 * PDH  / 32];
__device__ unsigned g_flag2  [PN2];      // h2 row claim/ready flags (0/1/2)
__device__ unsigned g_flag1  [PN1];      // h1s/mn1 row-claim flags

// ---------------- threefry2x32 (JAX-exact, 20 rounds) ------------------------
__host__ __device__ __forceinline__ void tf2x32(unsigned k0, unsigned k1,
                                                unsigned x0, unsigned x1,
                                                unsigned &o0, unsigned &o1) {
  unsigned ks2 = k0 ^ k1 ^ 0x1BD11BDAu;
#ifdef __CUDA_ARCH__
#define TF_ROT(x, r) __funnelshift_l((x), (x), (r))
#else
#define TF_ROT(x, r) (((x) << (r)) | ((x) >> (32 - (r))))
#endif
#define TF_RND(r) { x0 += x1; x1 = TF_ROT(x1, r); x1 ^= x0; }
  x0 += k0; x1 += k1;
  TF_RND(13) TF_RND(15) TF_RND(26) TF_RND(6)
  x0 += k1;  x1 += ks2 + 1u;
  TF_RND(17) TF_RND(29) TF_RND(16) TF_RND(24)
  x0 += ks2; x1 += k0 + 2u;
  TF_RND(13) TF_RND(15) TF_RND(26) TF_RND(6)
  x0 += k0;  x1 += k1 + 3u;
  TF_RND(17) TF_RND(29) TF_RND(16) TF_RND(24)
  x0 += k1;  x1 += ks2 + 4u;
  TF_RND(13) TF_RND(15) TF_RND(26) TF_RND(6)
  x0 += ks2; x1 += k0 + 5u;
#undef TF_RND
#undef TF_ROT
  o0 = x0; o1 = x1;
}

__device__ __forceinline__ unsigned ld_acq(const unsigned *p) {
  unsigned v;
  asm volatile("ld.global.acquire.gpu.b32 %0, [%1];" : "=r"(v) : "l"(p) : "memory");
  return v;
}

// ---------------- fused h2 maskgen + edge gather (E1 hop, C=128) --------------
// One warp per edge. First warp to CAS a src row computes its 128 mask bits
// (threefry + ballot), publishes them (store, fence, flag=2), and gathers from
// its register-resident bits. Duplicate warps spin (claimer is guaranteed
// resident: its CAS already executed) then read the published words.
// This interleaves ALU-bound and memory-bound warps inside one kernel.
__global__ __launch_bounds__(256) void fused_h2_gather_kernel(
    unsigned k0, unsigned k1, const float *__restrict__ feat,
    const int *__restrict__ rowmap, const int *__restrict__ src,
    const int *__restrict__ dst, unsigned *__restrict__ flag,
    unsigned *__restrict__ mask, float *__restrict__ sum,
    float *__restrict__ deg, int E) {
  int e = (blockIdx.x * blockDim.x + threadIdx.x) >> 5;
  if (e >= E) return;
  int lane = threadIdx.x & 31;
  int r = src[e];
  int d = dst[e];
  unsigned state = 0;
  if (lane == 0) {
    atomicAdd(&deg[d], 1.0f);
    state = atomicCAS(&flag[r], 0u, 1u);
  }
  state = __shfl_sync(0xffffffffu, state, 0);

  unsigned mw;  // mask word for this lane's 4 columns
  if (state == 0) {
    // claimer: compute 128 bits (4 evals/lane), publish
    unsigned base = (unsigned)r * 128u + (unsigned)lane;
    unsigned bw[4];
#pragma unroll
    for (int k = 0; k < 4; k++) {
      unsigned o0, o1;
      tf2x32(k0, k1, 0u, base + 32u * k, o0, o1);
      bw[k] = __ballot_sync(0xffffffffu, !((o0 ^ o1) >> 31));
    }
    if (lane == 0) {
      mask[r * 4 + 0] = bw[0];
      mask[r * 4 + 1] = bw[1];
      mask[r * 4 + 2] = bw[2];
      mask[r * 4 + 3] = bw[3];
      __threadfence();
      atomicExch(&flag[r], 2u);   // release (fence orders mask stores first)
    }
    mw = bw[lane >> 3];
  } else {
    if (state == 1) {
      // spin until published; only lane0 polls
      if (lane == 0) {
        while (ld_acq(&flag[r]) != 2u) { __nanosleep(64); }
      }
      __syncwarp();
    }
    __threadfence();  // acquire-side ordering before reading mask
    mw = mask[r * 4 + (lane >> 3)];
  }

  // gather: C=128, each lane handles columns lane*4..lane*4+3
  size_t g = (size_t)rowmap[r];
  int c0 = lane * 4;
  float4 v = *reinterpret_cast<const float4 *>(feat + g * 128 + c0);
  int sh = (lane & 7) * 4;
  float a0 = ((mw >> (sh + 0)) & 1u) ? 2.0f * v.x : 0.0f;
  float a1 = ((mw >> (sh + 1)) & 1u) ? 2.0f * v.y : 0.0f;
  float a2 = ((mw >> (sh + 2)) & 1u) ? 2.0f * v.z : 0.0f;
  float a3 = ((mw >> (sh + 3)) & 1u) ? 2.0f * v.w : 0.0f;
  float *s = sum + (size_t)d * 128 + c0;
  asm volatile("red.global.add.v4.f32 [%0], {%1,%2,%3,%4};"
               :: "l"(s), "f"(a0), "f"(a1), "f"(a2), "f"(a3) : "memory");
}

// ---------------- combined claim maskgen for h1s (4 words) + mn1 (8 words) ----
__global__ __launch_bounds__(256) void maskgen_pair_kernel(
    unsigned a0, unsigned a1, unsigned b0, unsigned b1,
    const int *__restrict__ src, int E, unsigned *__restrict__ flag,
    unsigned *__restrict__ maskA, unsigned *__restrict__ maskB) {
  int e = (blockIdx.x * blockDim.x + threadIdx.x) >> 5;
  if (e >= E) return;
  int lane = threadIdx.x & 31;
  int r = src[e];
  unsigned claimed = 0;
  if (lane == 0) claimed = (atomicExch(&flag[r], 1u) == 0u);
  claimed = __shfl_sync(0xffffffffu, claimed, 0);
  if (!claimed) return;
  unsigned baseA = (unsigned)r * 128u + (unsigned)lane;
  unsigned baseB = (unsigned)r * 256u + (unsigned)lane;
  unsigned keepA[4], keepB[8];
#pragma unroll
  for (int k = 0; k < 4; k++) {
    unsigned o0, o1;
    tf2x32(a0, a1, 0u, baseA + 32u * k, o0, o1);
    keepA[k] = !((o0 ^ o1) >> 31);
  }
#pragma unroll
  for (int k = 0; k < 8; k++) {
    unsigned o0, o1;
    tf2x32(b0, b1, 0u, baseB + 32u * k, o0, o1);
    keepB[k] = !((o0 ^ o1) >> 31);
  }
#pragma unroll
  for (int k = 0; k < 4; k++) {
    unsigned b = __ballot_sync(0xffffffffu, keepA[k]);
    if (lane == 0) maskA[r * 4 + k] = b;
  }
#pragma unroll
  for (int k = 0; k < 8; k++) {
    unsigned b = __ballot_sync(0xffffffffu, keepB[k]);
    if (lane == 0) maskB[r * 8 + k] = b;
  }
}

// ---------------- edge gather + segment-sum (one warp per edge) --------------
__global__ __launch_bounds__(256) void edge_gather_kernel(
    const float *__restrict__ feat, const int *__restrict__ rowmap,
    const int *__restrict__ src, const int *__restrict__ dst,
    const unsigned *__restrict__ mask, float *__restrict__ sum,
    float *__restrict__ deg, int E, int C) {
  int e = (blockIdx.x * blockDim.x + threadIdx.x) >> 5;
  if (e >= E) return;
  int lane = threadIdx.x & 31;
  int r = src[e];
  int d = dst[e];
  size_t g = rowmap ? (size_t)rowmap[r] : (size_t)r;
  if (deg && lane == 0) atomicAdd(&deg[d], 1.0f);
  const float4 *fr = reinterpret_cast<const float4 *>(feat + g * (size_t)C);
  for (int c0 = lane * 4; c0 < C; c0 += 128) {
    float4 v = fr[c0 >> 2];
    unsigned mw = mask[r * (C >> 5) + (c0 >> 5)];
    int sh = c0 & 31;
    float a0 = ((mw >> (sh + 0)) & 1u) ? 2.0f * v.x : 0.0f;
    float a1 = ((mw >> (sh + 1)) & 1u) ? 2.0f * v.y : 0.0f;
    float a2 = ((mw >> (sh + 2)) & 1u) ? 2.0f * v.z : 0.0f;
    float a3 = ((mw >> (sh + 3)) & 1u) ? 2.0f * v.w : 0.0f;
    float *s = sum + (size_t)d * C + c0;
    asm volatile("red.global.add.v4.f32 [%0], {%1,%2,%3,%4};"
                 :: "l"(s), "f"(a0), "f"(a1), "f"(a2), "f"(a3) : "memory");
  }
}

// ---------------- finalize with FUSED self-dropout RNG -----------------------
// relu(sum/deg + dropout(self)) in-place; the self mask bits are computed
// inline (4 threefry evals/thread) — no separate maskgen pass or storage.
__global__ __launch_bounds__(256) void finalize_rng_kernel(
    float *__restrict__ sum, const float *__restrict__ deg,
    const float *__restrict__ selfFeat, const int *__restrict__ rowmap,
    unsigned k0, unsigned k1, int Nr, int C) {
  int idx = blockIdx.x * blockDim.x + threadIdx.x;
  int perRow = C >> 2;
  if (idx >= Nr * perRow) return;
  int i = idx / perRow;
  int c0 = (idx - i * perRow) << 2;
  float d = deg[i];
  float inv = d > 0.f ? 1.0f / d : 0.f;
  size_t g = rowmap ? (size_t)rowmap[i] : (size_t)i;
  float4 hv = *reinterpret_cast<const float4 *>(selfFeat + g * (size_t)C + c0);
  unsigned jb = (unsigned)i * (unsigned)C + (unsigned)c0;
  unsigned keep[4];
#pragma unroll
  for (int t = 0; t < 4; t++) {
    unsigned o0, o1;
    tf2x32(k0, k1, 0u, jb + t, o0, o1);
    keep[t] = !((o0 ^ o1) >> 31);
  }
  float4 sv = *reinterpret_cast<const float4 *>(sum + (size_t)i * C + c0);
  float r0 = sv.x * inv + (keep[0] ? 2.f * hv.x : 0.f);
  float r1 = sv.y * inv + (keep[1] ? 2.f * hv.y : 0.f);
  float r2 = sv.z * inv + (keep[2] ? 2.f * hv.z : 0.f);
  float r3 = sv.w * inv + (keep[3] ? 2.f * hv.w : 0.f);
  float4 o = make_float4(fmaxf(r0, 0.f), fmaxf(r1, 0.f),
                         fmaxf(r2, 0.f), fmaxf(r3, 0.f));
  *reinterpret_cast<float4 *>(sum + (size_t)i * C + c0) = o;
}

// ---------------- SGEMM 128x64 tile, 8x4 microtile, bias (proven) ------------
__global__ __launch_bounds__(256) void sgemm_bias_128x64(
    const float *__restrict__ A, const float *__restrict__ B,
    const float *__restrict__ bias, float *__restrict__ C,
    int M, int N, int K) {
  __shared__ float As[16][132];
  __shared__ float Bs[16][68];
  int tid = threadIdx.x;
  int row0 = blockIdx.y * 128;
  int col0 = blockIdx.x * 64;
  int tr = tid >> 4;
  int tc = tid & 15;
  float acc[8][4];
#pragma unroll
  for (int i = 0; i < 8; i++)
#pragma unroll
    for (int j = 0; j < 4; j++) acc[i][j] = 0.f;

  int ar = tid >> 1;
  int ak = (tid & 1) * 8;
  int bk = tid >> 4;
  int bc = (tid & 15) * 4;

  for (int kk = 0; kk < K; kk += 16) {
    float4 a0, a1;
    if (row0 + ar < M) {
      const float *ap = A + (size_t)(row0 + ar) * K + kk + ak;
      a0 = *reinterpret_cast<const float4 *>(ap);
      a1 = *reinterpret_cast<const float4 *>(ap + 4);
    } else {
      a0 = make_float4(0.f, 0.f, 0.f, 0.f);
      a1 = a0;
    }
    As[ak + 0][ar] = a0.x; As[ak + 1][ar] = a0.y;
    As[ak + 2][ar] = a0.z; As[ak + 3][ar] = a0.w;
    As[ak + 4][ar] = a1.x; As[ak + 5][ar] = a1.y;
    As[ak + 6][ar] = a1.z; As[ak + 7][ar] = a1.w;
#pragma unroll
    for (int j = 0; j < 4; j++) {
      int c = col0 + bc + j;
      Bs[bk][bc + j] = (c < N) ? B[(size_t)(kk + bk) * N + c] : 0.f;
    }
    __syncthreads();
#pragma unroll
    for (int k = 0; k < 16; k++) {
      float a8[8], b4[4];
      *reinterpret_cast<float4 *>(a8)     = *reinterpret_cast<const float4 *>(&As[k][tr * 8]);
      *reinterpret_cast<float4 *>(a8 + 4) = *reinterpret_cast<const float4 *>(&As[k][tr * 8 + 4]);
      *reinterpret_cast<float4 *>(b4)     = *reinterpret_cast<const float4 *>(&Bs[k][tc * 4]);
#pragma unroll
      for (int i = 0; i < 8; i++)
#pragma unroll
        for (int j = 0; j < 4; j++) acc[i][j] += a8[i] * b4[j];
    }
    __syncthreads();
  }
#pragma unroll
  for (int i = 0; i < 8; i++) {
    int r = row0 + tr * 8 + i;
    if (r >= M) continue;
#pragma unroll
    for (int j = 0; j < 4; j++) {
      int c = col0 + tc * 4 + j;
      if (c < N) C[(size_t)r * N + c] = acc[i][j] + bias[c];
    }
  }
}

// ---------------- host orchestration -----------------------------------------
extern "C" void kernel_launch(void *const *d_in, const int *in_sizes, int n_in,
                              void *d_out, int out_size) {
  const float *features = (const float *)d_in[0];
  const int *s0 = (const int *)d_in[1];
  const int *s1 = (const int *)d_in[2];
  const int *s2 = (const int *)d_in[3];
  const int *src0 = (const int *)d_in[4];
  const int *dst0 = (const int *)d_in[5];
  const int *src1 = (const int *)d_in[6];
  const int *dst1 = (const int *)d_in[7];
  const float *W1 = (const float *)d_in[8];
  const float *b1 = (const float *)d_in[9];
  const float *W2 = (const float *)d_in[10];
  const float *b2 = (const float *)d_in[11];
  float *out = (float *)d_out;

  const int n0 = in_sizes[1];
  const int n1 = in_sizes[2];
  const int n2 = in_sizes[3];
  const int e0 = in_sizes[4];
  const int e1 = in_sizes[6];
  const int dh = in_sizes[9];          // 256
  const int dout = in_sizes[11];       // 47
  const int din = in_sizes[8] / dh;    // 128

  // ---- JAX key chain, threefry_partitionable=True semantics ----
  unsigned dk[3][2];
  tf2x32(0u, 42u, 0u, 0u, dk[0][0], dk[0][1]);
  tf2x32(0u, 42u, 0u, 1u, dk[1][0], dk[1][1]);
  tf2x32(0u, 42u, 0u, 2u, dk[2][0], dk[2][1]);
  unsigned kSrc[3][2], kSelf[3][2];
  for (int i = 0; i < 3; i++) {
    tf2x32(dk[i][0], dk[i][1], 0u, 0u, kSrc[i][0], kSrc[i][1]);
    tf2x32(dk[i][0], dk[i][1], 0u, 1u, kSelf[i][0], kSelf[i][1]);
  }

  // ---- scratch addresses ----
  void *p_sum1, *p_deg1, *p_n1, *p_sum0, *p_deg0, *p_n0, *p_sumA;
  void *p_flag2, *p_flag1, *p_mh2, *p_mh1s, *p_mn1;
  cudaGetSymbolAddress(&p_sum1, g_sum1);
  cudaGetSymbolAddress(&p_deg1, g_deg1);
  cudaGetSymbolAddress(&p_n1, g_n1);
  cudaGetSymbolAddress(&p_sum0, g_sum0);
  cudaGetSymbolAddress(&p_deg0, g_deg0);
  cudaGetSymbolAddress(&p_n0, g_n0);
  cudaGetSymbolAddress(&p_sumA, g_sumA);
  cudaGetSymbolAddress(&p_flag2, g_flag2);
  cudaGetSymbolAddress(&p_flag1, g_flag1);
  cudaGetSymbolAddress(&p_mh2, g_mask_h2);
  cudaGetSymbolAddress(&p_mh1s, g_mask_h1s);
  cudaGetSymbolAddress(&p_mn1, g_mask_n1);

  // ---- streams / events ----
  static cudaStream_t sB = nullptr, sC = nullptr;
  static cudaEvent_t evFork = nullptr, evZ0 = nullptr, evFused = nullptr,
                     evPair = nullptr, evC = nullptr;
  if (!sB) {
    cudaStreamCreateWithFlags(&sB, cudaStreamNonBlocking);
    cudaStreamCreateWithFlags(&sC, cudaStreamNonBlocking);
    cudaEventCreateWithFlags(&evFork, cudaEventDisableTiming);
    cudaEventCreateWithFlags(&evZ0, cudaEventDisableTiming);
    cudaEventCreateWithFlags(&evFused, cudaEventDisableTiming);
    cudaEventCreateWithFlags(&evPair, cudaEventDisableTiming);
    cudaEventCreateWithFlags(&evC, cudaEventDisableTiming);
  }
  cudaStream_t S = 0;  // legacy default = capture/origin stream

  // ---- S: zero what the fused kernel needs, then run it ----
  cudaMemsetAsync(p_flag2, 0, (size_t)n2 * sizeof(unsigned), S);
  cudaMemsetAsync(p_flag1, 0, (size_t)n1 * sizeof(unsigned), S);
  cudaMemsetAsync(p_sum1, 0, (size_t)n1 * din * sizeof(float), S);
  cudaMemsetAsync(p_deg1, 0, (size_t)n1 * sizeof(float), S);
  cudaEventRecord(evFork, S);
  {
    int blocks = (e1 * 32 + 255) / 256;
    fused_h2_gather_kernel<<<blocks, 256, 0, S>>>(
        kSrc[1][0], kSrc[1][1], features, s2, src1, dst1,
        (unsigned *)p_flag2, (unsigned *)p_mh2, (float *)p_sum1,
        (float *)p_deg1, e1);
  }
  cudaEventRecord(evFused, S);

  // ---- S: finalize1 (fused h1f RNG) + gemm1 ----
  {
    int fb = (n1 * (din / 4) + 255) / 256;
    finalize_rng_kernel<<<fb, 256, 0, S>>>((float *)p_sum1, (float *)p_deg1,
                                           features, s1, kSelf[1][0],
                                           kSelf[1][1], n1, din);
    dim3 grid((dh + 63) / 64, (n1 + 127) / 128);
    sgemm_bias_128x64<<<grid, 256, 0, S>>>((float *)p_sum1, W1, b1,
                                           (float *)p_n1, n1, dh, din);
  }

  // ---- sC: remaining accumulator memsets (overlap fused kernel) ----
  cudaStreamWaitEvent(sC, evFork, 0);
  cudaMemsetAsync(p_sum0, 0, (size_t)n0 * din * sizeof(float), sC);
  cudaMemsetAsync(p_deg0, 0, (size_t)n0 * sizeof(float), sC);
  cudaMemsetAsync(p_sumA, 0, (size_t)n0 * dh * sizeof(float), sC);
  cudaEventRecord(evZ0, sC);

  // ---- sB: h1s+mn1 claim maskgen, gated after fused (hides under gemm1) ----
  cudaStreamWaitEvent(sB, evFused, 0);
  {
    int blocks = (e0 * 32 + 255) / 256;
    maskgen_pair_kernel<<<blocks, 256, 0, sB>>>(
        kSrc[0][0], kSrc[0][1], kSrc[2][0], kSrc[2][1], src0, e0,
        (unsigned *)p_flag1, (unsigned *)p_mh1s, (unsigned *)p_mn1);
  }
  cudaEventRecord(evPair, sB);

  // ---- sC: a0 branch (hides under gemm1 on S) ----
  cudaStreamWaitEvent(sC, evPair, 0);
  {
    int blocks = (e0 * 32 + 255) / 256;
    edge_gather_kernel<<<blocks, 256, 0, sC>>>(features, s1, src0, dst0,
                                               (unsigned *)p_mh1s,
                                               (float *)p_sum0,
                                               (float *)p_deg0, e0, din);
    int fb = (n0 * (din / 4) + 255) / 256;
    finalize_rng_kernel<<<fb, 256, 0, sC>>>((float *)p_sum0, (float *)p_deg0,
                                            features, s0, kSelf[0][0],
                                            kSelf[0][1], n0, din);
    dim3 grid((dh + 63) / 64, (n0 + 127) / 128);
    sgemm_bias_128x64<<<grid, 256, 0, sC>>>((float *)p_sum0, W1, b1,
                                            (float *)p_n0, n0, dh, din);
  }
  cudaEventRecord(evC, sC);

  // ---- S: final layer ----
  cudaStreamWaitEvent(S, evPair, 0);  // mn1 mask
  cudaStreamWaitEvent(S, evZ0, 0);    // sumA zeroed
  {
    int blocks = (e0 * 32 + 255) / 256;
    edge_gather_kernel<<<blocks, 256, 0, S>>>((float *)p_n1, nullptr, src0,
                                              dst0, (unsigned *)p_mn1,
                                              (float *)p_sumA, nullptr, e0, dh);
  }
  cudaStreamWaitEvent(S, evC, 0);  // n0 + deg0 ready
  {
    int fb = (n0 * (dh / 4) + 255) / 256;
    finalize_rng_kernel<<<fb, 256, 0, S>>>((float *)p_sumA, (float *)p_deg0,
                                           (float *)p_n0, nullptr, kSelf[2][0],
                                           kSelf[2][1], n0, dh);
    dim3 grid((dout + 63) / 64, (n0 + 127) / 128);
    sgemm_bias_128x64<<<grid, 256, 0, S>>>((float *)p_sumA, W2, b2, out, n0,
                                           dout, dh);
  }
}